// round 1
// baseline (speedup 1.0000x reference)
#include <cuda_runtime.h>

// ---------------- static scratch (no allocations allowed) ----------------
#define MAXN0 600000
__device__ float g_x0[MAXN0 * 16];   // after first conv (+relu)
__device__ float g_x1[MAXN0 * 16];   // after pre conv (+relu)
__device__ float g_x2[MAXN0 * 32];   // after down conv (+relu)  (level-1)
__device__ float g_r0[MAXN0 * 32];   // resblock conv0 (+relu)
__device__ float g_r1[MAXN0 * 32];   // resblock conv1 (+bias +residual)

// ---------------- conv kernels (gather - GEMM - scatter-atomic) ----------

// C_IN=1 -> C_OUT=16, K offsets on grid.y. Two pairs per warp (half-warps).
template <int PPW>
__global__ void conv_c1_c16(const float* __restrict__ x,
                            const float* __restrict__ W,
                            const int* __restrict__ kin,
                            const int* __restrict__ kout,
                            float* __restrict__ out, int P, int n_out) {
    const int k = blockIdx.y;
    __shared__ float Ws[16];
    if (threadIdx.x < 16) Ws[threadIdx.x] = W[k * 16 + threadIdx.x];
    __syncthreads();

    const int warp = threadIdx.x >> 5;
    const int lane = threadIdx.x & 31;
    const int half = lane >> 4;
    const int c    = lane & 15;
    const long base = (long)k * P;
    int p = (blockIdx.x * (blockDim.x >> 5) + warp) * (2 * PPW) + half;

#pragma unroll 4
    for (int it = 0; it < PPW; ++it, p += 2) {
        if (p >= P) break;
        int j = __ldg(kout + base + p);
        if (j < n_out) {
            int i = __ldg(kin + base + p);
            float xv = __ldg(x + i);
            atomicAdd(&out[j * 16 + c], xv * Ws[c]);
        }
    }
}

// C_IN=16 -> C_OUT=16. Two pairs per warp. shfl width 16 broadcasts x row.
template <int PPW>
__global__ void conv_c16_c16(const float* __restrict__ x,
                             const float* __restrict__ W,
                             const int* __restrict__ kin,
                             const int* __restrict__ kout,
                             float* __restrict__ out, int P, int n_out) {
    const int k = blockIdx.y;
    __shared__ float Ws[256];
    for (int t = threadIdx.x; t < 256; t += blockDim.x) Ws[t] = W[k * 256 + t];
    __syncthreads();

    const int warp = threadIdx.x >> 5;
    const int lane = threadIdx.x & 31;
    const int half = lane >> 4;
    const int c    = lane & 15;
    const long base = (long)k * P;
    int p = (blockIdx.x * (blockDim.x >> 5) + warp) * (2 * PPW) + half;

    for (int it = 0; it < PPW; ++it, p += 2) {
        bool valid = (p < P);
        int j = valid ? __ldg(kout + base + p) : n_out;
        valid = (j < n_out);
        int i = valid ? __ldg(kin + base + p) : 0;
        float xv = __ldg(x + i * 16 + c);  // safe dummy gather when invalid
        float acc = 0.f;
#pragma unroll
        for (int cc = 0; cc < 16; ++cc)
            acc += __shfl_sync(0xffffffffu, xv, cc, 16) * Ws[cc * 16 + c];
        if (valid) atomicAdd(&out[j * 16 + c], acc);
    }
}

// C_IN=16 -> C_OUT=32 (downsample, K=8). One pair per warp.
template <int PPW>
__global__ void conv_c16_c32(const float* __restrict__ x,
                             const float* __restrict__ W,
                             const int* __restrict__ kin,
                             const int* __restrict__ kout,
                             float* __restrict__ out, int P, int n_out) {
    const int k = blockIdx.y;
    __shared__ float Ws[512];
    for (int t = threadIdx.x; t < 512; t += blockDim.x) Ws[t] = W[k * 512 + t];
    __syncthreads();

    const int warp = threadIdx.x >> 5;
    const int lane = threadIdx.x & 31;
    const long base = (long)k * P;
    int p = (blockIdx.x * (blockDim.x >> 5) + warp) * PPW;

    for (int it = 0; it < PPW; ++it, ++p) {
        bool valid = (p < P);
        int j = valid ? __ldg(kout + base + p) : n_out;
        valid = (j < n_out);
        int i = valid ? __ldg(kin + base + p) : 0;
        float xv = (lane < 16) ? __ldg(x + i * 16 + lane) : 0.f;
        float acc = 0.f;
#pragma unroll
        for (int cc = 0; cc < 16; ++cc)
            acc += __shfl_sync(0xffffffffu, xv, cc) * Ws[cc * 32 + lane];
        if (valid) atomicAdd(&out[j * 32 + lane], acc);
    }
}

// C_IN=32 -> C_OUT=32 (K=27). One pair per warp.
template <int PPW>
__global__ void conv_c32_c32(const float* __restrict__ x,
                             const float* __restrict__ W,
                             const int* __restrict__ kin,
                             const int* __restrict__ kout,
                             float* __restrict__ out, int P, int n_out) {
    const int k = blockIdx.y;
    __shared__ float Ws[1024];
    for (int t = threadIdx.x; t < 1024; t += blockDim.x) Ws[t] = W[k * 1024 + t];
    __syncthreads();

    const int warp = threadIdx.x >> 5;
    const int lane = threadIdx.x & 31;
    const long base = (long)k * P;
    int p = (blockIdx.x * (blockDim.x >> 5) + warp) * PPW;

    for (int it = 0; it < PPW; ++it, ++p) {
        bool valid = (p < P);
        int j = valid ? __ldg(kout + base + p) : n_out;
        valid = (j < n_out);
        int i = valid ? __ldg(kin + base + p) : 0;
        float xv = __ldg(x + i * 32 + lane);
        float acc = 0.f;
#pragma unroll
        for (int cc = 0; cc < 32; ++cc)
            acc += __shfl_sync(0xffffffffu, xv, cc) * Ws[cc * 32 + lane];
        if (valid) atomicAdd(&out[j * 32 + lane], acc);
    }
}

// ---------------- elementwise epilogues ----------------

// y = relu(y + b) over n rows of C=16; also copies result into cache.
__global__ void bias_relu_cache16(float* __restrict__ y, float* __restrict__ cache,
                                  const float* __restrict__ b, int total) {
    int i = blockIdx.x * blockDim.x + threadIdx.x;
    if (i >= total) return;
    float v = y[i] + b[i & 15];
    v = v > 0.f ? v : 0.f;
    y[i] = v;
    cache[i] = v;
}

template <int CM1>  // C-1 mask (15 or 31)
__global__ void bias_relu(float* __restrict__ y, const float* __restrict__ b, int total) {
    int i = blockIdx.x * blockDim.x + threadIdx.x;
    if (i >= total) return;
    float v = y[i] + b[i & CM1];
    y[i] = v > 0.f ? v : 0.f;
}

// y = y + b + skip   (residual, no relu), C=32
__global__ void residual32(float* __restrict__ y, const float* __restrict__ skip,
                           const float* __restrict__ b, int total) {
    int i = blockIdx.x * blockDim.x + threadIdx.x;
    if (i >= total) return;
    y[i] = y[i] + b[i & 31] + skip[i];
}

// y += b, C=32
__global__ void bias_add32(float* __restrict__ y, const float* __restrict__ b, int total) {
    int i = blockIdx.x * blockDim.x + threadIdx.x;
    if (i >= total) return;
    y[i] += b[i & 31];
}

// ---------------- host orchestration ----------------
extern "C" void kernel_launch(void* const* d_in, const int* in_sizes, int n_in,
                              void* d_out, int out_size) {
    const float* in_feats = (const float*)d_in[0];
    const float* W_first  = (const float*)d_in[1];
    const float* b_first  = (const float*)d_in[2];
    const float* W_pre    = (const float*)d_in[3];
    const float* b_pre    = (const float*)d_in[4];
    const float* W_down   = (const float*)d_in[5];
    const float* b_down   = (const float*)d_in[6];
    const float* W_r0     = (const float*)d_in[7];
    const float* b_r0     = (const float*)d_in[8];
    const float* W_r1     = (const float*)d_in[9];
    const float* b_r1     = (const float*)d_in[10];
    const float* W_fin    = (const float*)d_in[11];
    const float* b_fin    = (const float*)d_in[12];
    const int* km0_in  = (const int*)d_in[13];
    const int* km0_out = (const int*)d_in[14];
    const int* kmd_in  = (const int*)d_in[15];
    const int* kmd_out = (const int*)d_in[16];
    const int* km1_in  = (const int*)d_in[17];
    const int* km1_out = (const int*)d_in[18];

    const int n0 = in_sizes[0];            // C_IN = 1
    const int P0 = in_sizes[13] / 27;
    const int Pd = in_sizes[15] / 8;
    const int P1 = in_sizes[17] / 27;
    const int n1 = (out_size - n0 * 16) / 32;  // (out, cached) flattened in order

    float* out_fin    = (float*)d_out;                      // n1 x 32
    float* out_cached = (float*)d_out + (size_t)n1 * 32;    // n0 x 16

    float *x0, *x1, *x2, *r0, *r1;
    cudaGetSymbolAddress((void**)&x0, g_x0);
    cudaGetSymbolAddress((void**)&x1, g_x1);
    cudaGetSymbolAddress((void**)&x2, g_x2);
    cudaGetSymbolAddress((void**)&r0, g_r0);
    cudaGetSymbolAddress((void**)&r1, g_r1);

    constexpr int PPW = 16;     // pairs per warp (per half-warp for C16 kernels)
    const int THREADS = 256;    // 8 warps
    const int WARPS = THREADS / 32;

    // pair coverage per block:
    const int PB16 = WARPS * 2 * PPW;  // two pairs per warp slot (half-warps)
    const int PB32 = WARPS * PPW;

    auto ceil_div = [](int a, int b) { return (a + b - 1) / b; };

    // ---- first conv: C1 -> C16 (+relu, cache) ----
    cudaMemsetAsync(x0, 0, (size_t)n0 * 16 * sizeof(float), 0);
    {
        dim3 g(ceil_div(P0, PB16), 27);
        conv_c1_c16<PPW><<<g, THREADS, 0, 0>>>(in_feats, W_first, km0_in, km0_out, x0, P0, n0);
    }
    bias_relu_cache16<<<ceil_div(n0 * 16, 256), 256, 0, 0>>>(x0, out_cached, b_first, n0 * 16);

    // ---- pre conv: C16 -> C16 (+relu) ----
    cudaMemsetAsync(x1, 0, (size_t)n0 * 16 * sizeof(float), 0);
    {
        dim3 g(ceil_div(P0, PB16), 27);
        conv_c16_c16<PPW><<<g, THREADS, 0, 0>>>(x0, W_pre, km0_in, km0_out, x1, P0, n0);
    }
    bias_relu<15><<<ceil_div(n0 * 16, 256), 256, 0, 0>>>(x1, b_pre, n0 * 16);

    // ---- downsample conv: C16 -> C32, K=8 (+relu) ----
    cudaMemsetAsync(x2, 0, (size_t)n1 * 32 * sizeof(float), 0);
    {
        dim3 g(ceil_div(Pd, PB32), 8);
        conv_c16_c32<PPW><<<g, THREADS, 0, 0>>>(x1, W_down, kmd_in, kmd_out, x2, Pd, n1);
    }
    bias_relu<31><<<ceil_div(n1 * 32, 256), 256, 0, 0>>>(x2, b_down, n1 * 32);

    // ---- resblock conv0: C32 -> C32 (+relu) ----
    cudaMemsetAsync(r0, 0, (size_t)n1 * 32 * sizeof(float), 0);
    {
        dim3 g(ceil_div(P1, PB32), 27);
        conv_c32_c32<PPW><<<g, THREADS, 0, 0>>>(x2, W_r0, km1_in, km1_out, r0, P1, n1);
    }
    bias_relu<31><<<ceil_div(n1 * 32, 256), 256, 0, 0>>>(r0, b_r0, n1 * 32);

    // ---- resblock conv1: C32 -> C32 (+bias +residual) ----
    cudaMemsetAsync(r1, 0, (size_t)n1 * 32 * sizeof(float), 0);
    {
        dim3 g(ceil_div(P1, PB32), 27);
        conv_c32_c32<PPW><<<g, THREADS, 0, 0>>>(r0, W_r1, km1_in, km1_out, r1, P1, n1);
    }
    residual32<<<ceil_div(n1 * 32, 256), 256, 0, 0>>>(r1, x2, b_r1, n1 * 32);

    // ---- final conv: C32 -> C32 into d_out (+bias, no relu) ----
    cudaMemsetAsync(out_fin, 0, (size_t)n1 * 32 * sizeof(float), 0);
    {
        dim3 g(ceil_div(P1, PB32), 27);
        conv_c32_c32<PPW><<<g, THREADS, 0, 0>>>(r1, W_fin, km1_in, km1_out, out_fin, P1, n1);
    }
    bias_add32<<<ceil_div(n1 * 32, 256), 256, 0, 0>>>(out_fin, b_fin, n1 * 32);
}

// round 2
// speedup vs baseline: 2.4862x; 2.4862x over previous
#include <cuda_runtime.h>

// ---------------- static scratch (no allocations allowed) ----------------
#define MAXN0 600000
__device__ float g_x0[MAXN0 * 16];       // after first conv (+relu)
__device__ float g_x1[MAXN0 * 16];       // after pre conv (+relu)
__device__ float g_x2[MAXN0 * 32];       // after down conv (+relu)
__device__ float g_r0[MAXN0 * 32];       // resblock conv0 (+relu)
__device__ float g_r1[MAXN0 * 32];       // resblock conv1 (+bias+residual)
__device__ int   g_gi0[27 * MAXN0];      // inverse map, level 0 (27 offsets)
__device__ int   g_gid[8 * MAXN0];       // inverse map, downsample (8 offsets)
__device__ int   g_gi1[27 * MAXN0];      // inverse map, level 1 (27 offsets)

// ---------------- inverse-map build (scatter, no collisions within k) ----
__global__ void build_gi(const int* __restrict__ kin, const int* __restrict__ kout,
                         int* __restrict__ gi, int P, int n) {
    const int k = blockIdx.y;
    int p = blockIdx.x * blockDim.x + threadIdx.x;
    if (p >= P) return;
    const size_t base = (size_t)k * P;
    int j = kout[base + p];
    if (j < n) gi[(size_t)k * n + j] = kin[base + p];
}

// ---------------- gather convs, epilogue fused --------------------------

// C_IN=1 -> C_OUT=16. One thread per (output, channel). Fused bias+relu+cache.
__global__ void conv1_16(const float* __restrict__ x, const float* __restrict__ W,
                         const int* __restrict__ gi, const float* __restrict__ b,
                         float* __restrict__ out, float* __restrict__ cache, int n) {
    __shared__ float Ws[27 * 16];
    for (int t = threadIdx.x; t < 27 * 16; t += blockDim.x) Ws[t] = W[t];
    __syncthreads();
    int tid = blockIdx.x * blockDim.x + threadIdx.x;
    int j = tid >> 4, c = tid & 15;
    if (j >= n) return;
    float acc = __ldg(b + c);
#pragma unroll
    for (int k = 0; k < 27; ++k) {
        int i = __ldg(gi + (size_t)k * n + j);
        if (i >= 0) acc += __ldg(x + i) * Ws[k * 16 + c];
    }
    float v = acc > 0.f ? acc : 0.f;
    out[(size_t)j * 16 + c] = v;
    cache[(size_t)j * 16 + c] = v;
}

// C_IN=16 -> C_OUT=16. Half-warp per output, JB outputs per half-warp. bias+relu.
template <int JB>
__global__ void conv16_16(const float* __restrict__ x, const float* __restrict__ W,
                          const int* __restrict__ gi, const float* __restrict__ b,
                          float* __restrict__ out, int n) {
    const int warp = threadIdx.x >> 5, lane = threadIdx.x & 31;
    const int half = lane >> 4, c = lane & 15;
    const unsigned hm = 0xFFFFu << (half * 16);
    const int hw = (blockIdx.x * (blockDim.x >> 5) + warp) * 2 + half;
    const int j0 = hw * JB;
    if (j0 >= n && ((hw ^ 1) * JB) >= n) return;  // both halves done -> whole warp exits
    float acc[JB];
#pragma unroll
    for (int jj = 0; jj < JB; ++jj) acc[jj] = 0.f;

    for (int k = 0; k < 27; ++k) {
        const float* Wk = W + k * 256;
        float w[16];
#pragma unroll
        for (int cc = 0; cc < 16; ++cc) w[cc] = __ldg(Wk + cc * 16 + c);
        const int* gik = gi + (size_t)k * n;
#pragma unroll
        for (int jj = 0; jj < JB; ++jj) {
            int j = j0 + jj;
            int i = (j < n) ? __ldg(gik + j) : -1;
            if (i >= 0) {
                float xv = __ldg(x + (size_t)i * 16 + c);
#pragma unroll
                for (int cc = 0; cc < 16; ++cc)
                    acc[jj] += __shfl_sync(hm, xv, cc, 16) * w[cc];
            }
        }
    }
    float bb = __ldg(b + c);
#pragma unroll
    for (int jj = 0; jj < JB; ++jj) {
        int j = j0 + jj;
        if (j < n) {
            float v = acc[jj] + bb;
            out[(size_t)j * 16 + c] = v > 0.f ? v : 0.f;
        }
    }
}

// C_IN=16 -> C_OUT=32 (downsample, K=8). Warp per output, JB outputs. bias+relu.
template <int JB>
__global__ void conv16_32(const float* __restrict__ x, const float* __restrict__ W,
                          const int* __restrict__ gi, const float* __restrict__ b,
                          float* __restrict__ out, int n) {
    const int warp = threadIdx.x >> 5, lane = threadIdx.x & 31;
    const int j0 = (blockIdx.x * (blockDim.x >> 5) + warp) * JB;
    if (j0 >= n) return;
    float acc[JB];
#pragma unroll
    for (int jj = 0; jj < JB; ++jj) acc[jj] = 0.f;

    for (int k = 0; k < 8; ++k) {
        const float* Wk = W + k * 512;
        float w[16];
#pragma unroll
        for (int cc = 0; cc < 16; ++cc) w[cc] = __ldg(Wk + cc * 32 + lane);
        const int* gik = gi + (size_t)k * n;
#pragma unroll
        for (int jj = 0; jj < JB; ++jj) {
            int j = j0 + jj;
            int i = (j < n) ? __ldg(gik + j) : -1;
            if (i >= 0) {
                float xv = (lane < 16) ? __ldg(x + (size_t)i * 16 + lane) : 0.f;
#pragma unroll
                for (int cc = 0; cc < 16; ++cc)
                    acc[jj] += __shfl_sync(0xffffffffu, xv, cc) * w[cc];
            }
        }
    }
    float bb = __ldg(b + lane);
#pragma unroll
    for (int jj = 0; jj < JB; ++jj) {
        int j = j0 + jj;
        if (j < n) {
            float v = acc[jj] + bb;
            out[(size_t)j * 32 + lane] = v > 0.f ? v : 0.f;
        }
    }
}

// C_IN=32 -> C_OUT=32 (K=27). Warp per output, JB outputs per warp.
// EPI: 0 = bias+relu, 1 = bias+residual, 2 = bias only.
template <int EPI, int JB>
__global__ void conv32_32(const float* __restrict__ x, const float* __restrict__ W,
                          const int* __restrict__ gi, const float* __restrict__ b,
                          const float* __restrict__ skip, float* __restrict__ out, int n) {
    const int warp = threadIdx.x >> 5, lane = threadIdx.x & 31;
    const int j0 = (blockIdx.x * (blockDim.x >> 5) + warp) * JB;
    if (j0 >= n) return;
    float acc[JB];
#pragma unroll
    for (int jj = 0; jj < JB; ++jj) acc[jj] = 0.f;

    for (int k = 0; k < 27; ++k) {
        const float* Wk = W + k * 1024;
        float w[32];
#pragma unroll
        for (int cc = 0; cc < 32; ++cc) w[cc] = __ldg(Wk + cc * 32 + lane);
        const int* gik = gi + (size_t)k * n;
#pragma unroll
        for (int jj = 0; jj < JB; ++jj) {
            int j = j0 + jj;
            int i = (j < n) ? __ldg(gik + j) : -1;
            if (i >= 0) {
                float xv = __ldg(x + (size_t)i * 32 + lane);
#pragma unroll
                for (int cc = 0; cc < 32; ++cc)
                    acc[jj] += __shfl_sync(0xffffffffu, xv, cc) * w[cc];
            }
        }
    }
    float bb = __ldg(b + lane);
#pragma unroll
    for (int jj = 0; jj < JB; ++jj) {
        int j = j0 + jj;
        if (j < n) {
            float v = acc[jj] + bb;
            if (EPI == 0) v = v > 0.f ? v : 0.f;
            if (EPI == 1) v += __ldg(skip + (size_t)j * 32 + lane);
            out[(size_t)j * 32 + lane] = v;
        }
    }
}

// ---------------- host orchestration ----------------
extern "C" void kernel_launch(void* const* d_in, const int* in_sizes, int n_in,
                              void* d_out, int out_size) {
    const float* in_feats = (const float*)d_in[0];
    const float* W_first  = (const float*)d_in[1];
    const float* b_first  = (const float*)d_in[2];
    const float* W_pre    = (const float*)d_in[3];
    const float* b_pre    = (const float*)d_in[4];
    const float* W_down   = (const float*)d_in[5];
    const float* b_down   = (const float*)d_in[6];
    const float* W_r0     = (const float*)d_in[7];
    const float* b_r0     = (const float*)d_in[8];
    const float* W_r1     = (const float*)d_in[9];
    const float* b_r1     = (const float*)d_in[10];
    const float* W_fin    = (const float*)d_in[11];
    const float* b_fin    = (const float*)d_in[12];
    const int* km0_in  = (const int*)d_in[13];
    const int* km0_out = (const int*)d_in[14];
    const int* kmd_in  = (const int*)d_in[15];
    const int* kmd_out = (const int*)d_in[16];
    const int* km1_in  = (const int*)d_in[17];
    const int* km1_out = (const int*)d_in[18];

    const int n0 = in_sizes[0];
    const int P0 = in_sizes[13] / 27;
    const int Pd = in_sizes[15] / 8;
    const int P1 = in_sizes[17] / 27;
    const int n1 = (out_size - n0 * 16) / 32;  // (out, cached) flattened in order

    float* out_fin    = (float*)d_out;                    // n1 x 32
    float* out_cached = (float*)d_out + (size_t)n1 * 32;  // n0 x 16

    float *x0, *x1, *x2, *r0, *r1;
    int *gi0, *gid, *gi1;
    cudaGetSymbolAddress((void**)&x0, g_x0);
    cudaGetSymbolAddress((void**)&x1, g_x1);
    cudaGetSymbolAddress((void**)&x2, g_x2);
    cudaGetSymbolAddress((void**)&r0, g_r0);
    cudaGetSymbolAddress((void**)&r1, g_r1);
    cudaGetSymbolAddress((void**)&gi0, g_gi0);
    cudaGetSymbolAddress((void**)&gid, g_gid);
    cudaGetSymbolAddress((void**)&gi1, g_gi1);

    auto ceil_div = [](int a, int b) { return (a + b - 1) / b; };
    const int T = 256;
    const int WARPS = T / 32;
    constexpr int JB = 4;

    // ---- build inverse maps (pad entries j==n are skipped; -1 = no pair) ----
    cudaMemsetAsync(gi0, 0xFF, (size_t)27 * n0 * sizeof(int), 0);
    cudaMemsetAsync(gid, 0xFF, (size_t)8 * n1 * sizeof(int), 0);
    cudaMemsetAsync(gi1, 0xFF, (size_t)27 * n1 * sizeof(int), 0);
    {
        dim3 g0(ceil_div(P0, T), 27);
        build_gi<<<g0, T>>>(km0_in, km0_out, gi0, P0, n0);
        dim3 gd(ceil_div(Pd, T), 8);
        build_gi<<<gd, T>>>(kmd_in, kmd_out, gid, Pd, n1);
        dim3 g1(ceil_div(P1, T), 27);
        build_gi<<<g1, T>>>(km1_in, km1_out, gi1, P1, n1);
    }

    // ---- first conv: 1 -> 16, +bias +relu, writes x0 and cache ----
    conv1_16<<<ceil_div(n0 * 16, T), T>>>(in_feats, W_first, gi0, b_first, x0, out_cached, n0);

    // ---- pre conv: 16 -> 16, +bias +relu ----
    conv16_16<JB><<<ceil_div(n0, WARPS * 2 * JB), T>>>(x0, W_pre, gi0, b_pre, x1, n0);

    // ---- downsample conv: 16 -> 32 (K=8), +bias +relu ----
    conv16_32<JB><<<ceil_div(n1, WARPS * JB), T>>>(x1, W_down, gid, b_down, x2, n1);

    // ---- resblock conv0: 32 -> 32, +bias +relu ----
    conv32_32<0, JB><<<ceil_div(n1, WARPS * JB), T>>>(x2, W_r0, gi1, b_r0, nullptr, r0, n1);

    // ---- resblock conv1: 32 -> 32, +bias +residual ----
    conv32_32<1, JB><<<ceil_div(n1, WARPS * JB), T>>>(r0, W_r1, gi1, b_r1, x2, r1, n1);

    // ---- final conv: 32 -> 32, +bias, into d_out ----
    conv32_32<2, JB><<<ceil_div(n1, WARPS * JB), T>>>(r1, W_fin, gi1, b_fin, nullptr, out_fin, n1);
}

// round 3
// speedup vs baseline: 3.5695x; 1.4357x over previous
#include <cuda_runtime.h>

// ---------------- static scratch (no allocations allowed) ----------------
#define MAXN0 600000
__device__ float g_x0[MAXN0 * 16];
__device__ float g_x1[MAXN0 * 16];
__device__ float g_x2[MAXN0 * 32];
__device__ float g_r0[MAXN0 * 32];
__device__ float g_r1[MAXN0 * 32];
__device__ int   g_gi0[27 * MAXN0];
__device__ int   g_gid[8 * MAXN0];
__device__ int   g_gi1[27 * MAXN0];

typedef unsigned long long u64;
union F2U { u64 u; float2 f; };

__device__ __forceinline__ u64 bcast2(float s) {
    u64 r; asm("mov.b64 %0, {%1, %1};" : "=l"(r) : "r"(__float_as_uint(s))); return r;
}
__device__ __forceinline__ void ffma2(u64& a, u64 x, u64 w) {
    asm("fma.rn.f32x2 %0, %1, %2, %3;" : "=l"(a) : "l"(x), "l"(w), "l"(a));
}
__device__ __forceinline__ u64 packf2(float lo, float hi) {
    u64 r; asm("mov.b64 %0, {%1, %2};" : "=l"(r) : "r"(__float_as_uint(lo)), "r"(__float_as_uint(hi))); return r;
}

// ---------------- inverse-map build ----------------
__global__ void build_gi(const int* __restrict__ kin, const int* __restrict__ kout,
                         int* __restrict__ gi, int P, int n) {
    const int k = blockIdx.y;
    int p = blockIdx.x * blockDim.x + threadIdx.x;
    if (p >= P) return;
    const size_t base = (size_t)k * P;
    int j = kout[base + p];
    if (j < n) gi[(size_t)k * n + j] = kin[base + p];
}

// ---------------- conv 1->16: one thread per output row -----------------
__global__ __launch_bounds__(256) void conv1_16(const float* __restrict__ x,
        const float* __restrict__ W, const int* __restrict__ gi,
        const float* __restrict__ b, float* __restrict__ out,
        float* __restrict__ cache, int n) {
    __shared__ float Ws[27 * 16];
    for (int t = threadIdx.x; t < 27 * 16; t += 256) Ws[t] = W[t];
    __syncthreads();
    int j = blockIdx.x * 256 + threadIdx.x;
    if (j >= n) return;
    float acc[16];
#pragma unroll
    for (int c = 0; c < 16; ++c) acc[c] = __ldg(b + c);
#pragma unroll
    for (int k = 0; k < 27; ++k) {
        int i = __ldg(gi + (size_t)k * n + j);
        if (i >= 0) {
            float xv = __ldg(x + i);
#pragma unroll
            for (int c = 0; c < 16; ++c) acc[c] += xv * Ws[k * 16 + c];
        }
    }
    float4* o4 = (float4*)(out + (size_t)j * 16);
    float4* c4 = (float4*)(cache + (size_t)j * 16);
#pragma unroll
    for (int r = 0; r < 4; ++r) {
        float4 v = make_float4(fmaxf(acc[4*r], 0.f), fmaxf(acc[4*r+1], 0.f),
                               fmaxf(acc[4*r+2], 0.f), fmaxf(acc[4*r+3], 0.f));
        o4[r] = v; c4[r] = v;
    }
}

// ---------------- conv 16->16 (K=27): lane owns output row --------------
__global__ __launch_bounds__(256) void conv16_16(const float* __restrict__ x,
        const float* __restrict__ W, const int* __restrict__ gi,
        const float* __restrict__ b, float* __restrict__ out, int n) {
    __shared__ float4 Ws4[27 * 64];          // 27 * 256 floats
    const float4* Wg = (const float4*)W;
    for (int t = threadIdx.x; t < 27 * 64; t += 256) Ws4[t] = Wg[t];
    __syncthreads();
    int j = blockIdx.x * 256 + threadIdx.x;
    bool jv = j < n;
    u64 acc[8];
#pragma unroll
    for (int p = 0; p < 8; ++p) acc[p] = 0ull;

    for (int k = 0; k < 27; ++k) {
        int i = jv ? __ldg(gi + (size_t)k * n + j) : -1;
        if (!__ballot_sync(0xffffffffu, i >= 0)) continue;
        float4 X[4];
        if (i >= 0) {
            const float4* xr = (const float4*)(x + (size_t)i * 16);
#pragma unroll
            for (int q = 0; q < 4; ++q) X[q] = __ldg(xr + q);
        } else {
#pragma unroll
            for (int q = 0; q < 4; ++q) X[q] = make_float4(0.f, 0.f, 0.f, 0.f);
        }
        const float4* Wk = Ws4 + k * 64;
#pragma unroll
        for (int q = 0; q < 4; ++q) {
            float xs[4] = {X[q].x, X[q].y, X[q].z, X[q].w};
#pragma unroll
            for (int s = 0; s < 4; ++s) {
                int cc = q * 4 + s;
                u64 xx = bcast2(xs[s]);
                const float4* wrow = Wk + cc * 4;
#pragma unroll
                for (int r = 0; r < 4; ++r) {
                    float4 wv = wrow[r];
                    ffma2(acc[2*r],   xx, packf2(wv.x, wv.y));
                    ffma2(acc[2*r+1], xx, packf2(wv.z, wv.w));
                }
            }
        }
    }
    if (jv) {
        const float4* b4 = (const float4*)b;
        float4* o4 = (float4*)(out + (size_t)j * 16);
#pragma unroll
        for (int r = 0; r < 4; ++r) {
            F2U a0, a1; a0.u = acc[2*r]; a1.u = acc[2*r+1];
            float4 bb = __ldg(b4 + r);
            float4 v = make_float4(fmaxf(a0.f.x + bb.x, 0.f), fmaxf(a0.f.y + bb.y, 0.f),
                                   fmaxf(a1.f.x + bb.z, 0.f), fmaxf(a1.f.y + bb.w, 0.f));
            o4[r] = v;
        }
    }
}

// ---------------- conv 16->32 (K=8, downsample) -------------------------
__global__ __launch_bounds__(256) void conv16_32(const float* __restrict__ x,
        const float* __restrict__ W, const int* __restrict__ gi,
        const float* __restrict__ b, float* __restrict__ out, int n) {
    __shared__ float4 Ws4[8 * 128];          // 8 * 512 floats
    const float4* Wg = (const float4*)W;
    for (int t = threadIdx.x; t < 8 * 128; t += 256) Ws4[t] = Wg[t];
    __syncthreads();
    int j = blockIdx.x * 256 + threadIdx.x;
    bool jv = j < n;
    u64 acc[16];
#pragma unroll
    for (int p = 0; p < 16; ++p) acc[p] = 0ull;

    for (int k = 0; k < 8; ++k) {
        int i = jv ? __ldg(gi + (size_t)k * n + j) : -1;
        if (!__ballot_sync(0xffffffffu, i >= 0)) continue;
        float4 X[4];
        if (i >= 0) {
            const float4* xr = (const float4*)(x + (size_t)i * 16);
#pragma unroll
            for (int q = 0; q < 4; ++q) X[q] = __ldg(xr + q);
        } else {
#pragma unroll
            for (int q = 0; q < 4; ++q) X[q] = make_float4(0.f, 0.f, 0.f, 0.f);
        }
        const float4* Wk = Ws4 + k * 128;
#pragma unroll
        for (int q = 0; q < 4; ++q) {
            float xs[4] = {X[q].x, X[q].y, X[q].z, X[q].w};
#pragma unroll
            for (int s = 0; s < 4; ++s) {
                int cc = q * 4 + s;
                u64 xx = bcast2(xs[s]);
                const float4* wrow = Wk + cc * 8;
#pragma unroll
                for (int r = 0; r < 8; ++r) {
                    float4 wv = wrow[r];
                    ffma2(acc[2*r],   xx, packf2(wv.x, wv.y));
                    ffma2(acc[2*r+1], xx, packf2(wv.z, wv.w));
                }
            }
        }
    }
    if (jv) {
        const float4* b4 = (const float4*)b;
        float4* o4 = (float4*)(out + (size_t)j * 32);
#pragma unroll
        for (int r = 0; r < 8; ++r) {
            F2U a0, a1; a0.u = acc[2*r]; a1.u = acc[2*r+1];
            float4 bb = __ldg(b4 + r);
            float4 v = make_float4(fmaxf(a0.f.x + bb.x, 0.f), fmaxf(a0.f.y + bb.y, 0.f),
                                   fmaxf(a1.f.x + bb.z, 0.f), fmaxf(a1.f.y + bb.w, 0.f));
            o4[r] = v;
        }
    }
}

// ---------------- conv 32->32 (K=27): lane owns output row --------------
// EPI: 0 = bias+relu, 1 = bias+residual, 2 = bias only.
template <int EPI>
__global__ __launch_bounds__(256) void conv32_32(const float* __restrict__ x,
        const float* __restrict__ W, const int* __restrict__ gi,
        const float* __restrict__ b, const float* __restrict__ skip,
        float* __restrict__ out, int n) {
    extern __shared__ float4 Ws4[];          // 27 * 256 float4 = 108 KB
    const float4* Wg = (const float4*)W;
    for (int t = threadIdx.x; t < 27 * 256; t += 256) Ws4[t] = Wg[t];
    __syncthreads();
    int j = blockIdx.x * 256 + threadIdx.x;
    bool jv = j < n;
    u64 acc[16];
#pragma unroll
    for (int p = 0; p < 16; ++p) acc[p] = 0ull;

    for (int k = 0; k < 27; ++k) {
        int i = jv ? __ldg(gi + (size_t)k * n + j) : -1;
        if (!__ballot_sync(0xffffffffu, i >= 0)) continue;
        float4 X[8];
        if (i >= 0) {
            const float4* xr = (const float4*)(x + (size_t)i * 32);
#pragma unroll
            for (int q = 0; q < 8; ++q) X[q] = __ldg(xr + q);
        } else {
#pragma unroll
            for (int q = 0; q < 8; ++q) X[q] = make_float4(0.f, 0.f, 0.f, 0.f);
        }
        const float4* Wk = Ws4 + k * 256;
#pragma unroll
        for (int q = 0; q < 8; ++q) {
            float xs[4] = {X[q].x, X[q].y, X[q].z, X[q].w};
#pragma unroll
            for (int s = 0; s < 4; ++s) {
                int cc = q * 4 + s;
                u64 xx = bcast2(xs[s]);
                const float4* wrow = Wk + cc * 8;
#pragma unroll
                for (int r = 0; r < 8; ++r) {
                    float4 wv = wrow[r];
                    ffma2(acc[2*r],   xx, packf2(wv.x, wv.y));
                    ffma2(acc[2*r+1], xx, packf2(wv.z, wv.w));
                }
            }
        }
    }
    if (jv) {
        const float4* b4 = (const float4*)b;
        float4* o4 = (float4*)(out + (size_t)j * 32);
        const float4* s4 = (EPI == 1) ? (const float4*)(skip + (size_t)j * 32) : nullptr;
#pragma unroll
        for (int r = 0; r < 8; ++r) {
            F2U a0, a1; a0.u = acc[2*r]; a1.u = acc[2*r+1];
            float4 bb = __ldg(b4 + r);
            float4 v = make_float4(a0.f.x + bb.x, a0.f.y + bb.y, a1.f.x + bb.z, a1.f.y + bb.w);
            if (EPI == 0) {
                v.x = fmaxf(v.x, 0.f); v.y = fmaxf(v.y, 0.f);
                v.z = fmaxf(v.z, 0.f); v.w = fmaxf(v.w, 0.f);
            }
            if (EPI == 1) {
                float4 sv = __ldg(s4 + r);
                v.x += sv.x; v.y += sv.y; v.z += sv.z; v.w += sv.w;
            }
            o4[r] = v;
        }
    }
}

// ---------------- host orchestration ----------------
extern "C" void kernel_launch(void* const* d_in, const int* in_sizes, int n_in,
                              void* d_out, int out_size) {
    const float* in_feats = (const float*)d_in[0];
    const float* W_first  = (const float*)d_in[1];
    const float* b_first  = (const float*)d_in[2];
    const float* W_pre    = (const float*)d_in[3];
    const float* b_pre    = (const float*)d_in[4];
    const float* W_down   = (const float*)d_in[5];
    const float* b_down   = (const float*)d_in[6];
    const float* W_r0     = (const float*)d_in[7];
    const float* b_r0     = (const float*)d_in[8];
    const float* W_r1     = (const float*)d_in[9];
    const float* b_r1     = (const float*)d_in[10];
    const float* W_fin    = (const float*)d_in[11];
    const float* b_fin    = (const float*)d_in[12];
    const int* km0_in  = (const int*)d_in[13];
    const int* km0_out = (const int*)d_in[14];
    const int* kmd_in  = (const int*)d_in[15];
    const int* kmd_out = (const int*)d_in[16];
    const int* km1_in  = (const int*)d_in[17];
    const int* km1_out = (const int*)d_in[18];

    const int n0 = in_sizes[0];
    const int P0 = in_sizes[13] / 27;
    const int Pd = in_sizes[15] / 8;
    const int P1 = in_sizes[17] / 27;
    const int n1 = (out_size - n0 * 16) / 32;

    float* out_fin    = (float*)d_out;
    float* out_cached = (float*)d_out + (size_t)n1 * 32;

    float *x0, *x1, *x2, *r0, *r1;
    int *gi0, *gid, *gi1;
    cudaGetSymbolAddress((void**)&x0, g_x0);
    cudaGetSymbolAddress((void**)&x1, g_x1);
    cudaGetSymbolAddress((void**)&x2, g_x2);
    cudaGetSymbolAddress((void**)&r0, g_r0);
    cudaGetSymbolAddress((void**)&r1, g_r1);
    cudaGetSymbolAddress((void**)&gi0, g_gi0);
    cudaGetSymbolAddress((void**)&gid, g_gid);
    cudaGetSymbolAddress((void**)&gi1, g_gi1);

    const int SMEM32 = 27 * 256 * sizeof(float4);  // 110592 B
    static bool attr_done = false;
    if (!attr_done) {
        cudaFuncSetAttribute(conv32_32<0>, cudaFuncAttributeMaxDynamicSharedMemorySize, SMEM32);
        cudaFuncSetAttribute(conv32_32<1>, cudaFuncAttributeMaxDynamicSharedMemorySize, SMEM32);
        cudaFuncSetAttribute(conv32_32<2>, cudaFuncAttributeMaxDynamicSharedMemorySize, SMEM32);
        attr_done = true;
    }

    auto ceil_div = [](int a, int b) { return (a + b - 1) / b; };
    const int T = 256;

    // ---- build inverse maps ----
    cudaMemsetAsync(gi0, 0xFF, (size_t)27 * n0 * sizeof(int), 0);
    cudaMemsetAsync(gid, 0xFF, (size_t)8 * n1 * sizeof(int), 0);
    cudaMemsetAsync(gi1, 0xFF, (size_t)27 * n1 * sizeof(int), 0);
    {
        dim3 g0(ceil_div(P0, T), 27);
        build_gi<<<g0, T>>>(km0_in, km0_out, gi0, P0, n0);
        dim3 gd(ceil_div(Pd, T), 8);
        build_gi<<<gd, T>>>(kmd_in, kmd_out, gid, Pd, n1);
        dim3 g1(ceil_div(P1, T), 27);
        build_gi<<<g1, T>>>(km1_in, km1_out, gi1, P1, n1);
    }

    // ---- first conv: 1 -> 16, +bias +relu, writes x0 and cache ----
    conv1_16<<<ceil_div(n0, T), T>>>(in_feats, W_first, gi0, b_first, x0, out_cached, n0);

    // ---- pre conv: 16 -> 16, +bias +relu ----
    conv16_16<<<ceil_div(n0, T), T>>>(x0, W_pre, gi0, b_pre, x1, n0);

    // ---- downsample conv: 16 -> 32 (K=8), +bias +relu ----
    conv16_32<<<ceil_div(n1, T), T>>>(x1, W_down, gid, b_down, x2, n1);

    // ---- resblock conv0: 32 -> 32, +bias +relu ----
    conv32_32<0><<<ceil_div(n1, T), T, SMEM32>>>(x2, W_r0, gi1, b_r0, nullptr, r0, n1);

    // ---- resblock conv1: 32 -> 32, +bias +residual ----
    conv32_32<1><<<ceil_div(n1, T), T, SMEM32>>>(r0, W_r1, gi1, b_r1, x2, r1, n1);

    // ---- final conv: 32 -> 32, +bias, into d_out ----
    conv32_32<2><<<ceil_div(n1, T), T, SMEM32>>>(r1, W_fin, gi1, b_fin, nullptr, out_fin, n1);
}